// round 15
// baseline (speedup 1.0000x reference)
#include <cuda_runtime.h>
#include <cuda_fp16.h>
#include <cstdint>

#define BB 2
#define SS 2048
#define DD 1024
#define HH 16
#define DKH 64
#define BHH (BB*HH)

// ---------------------------------------------------------------------------
// Scratch: single fp16 everywhere.
// ---------------------------------------------------------------------------
__device__ __half g_x [BB * SS * DD];
__device__ __half g_w [3 * HH * DKH * DD];   // [(proj*16+h)*64+n][k]
__device__ __half g_q [BHH * SS * DKH];      // [bh][s][64] (UNscaled)
__device__ __half g_k [BHH * SS * DKH];
__device__ __half g_v [BHH * SS * DKH];
__device__ __half g_c [BB * SS * HH * DKH];  // ctx [token][1024]
__device__ __half g_wo[DD * DD];             // Wo^T [n][k]

// ---------------------------------------------------------------------------
// Helpers
// ---------------------------------------------------------------------------
__device__ __forceinline__ uint32_t smem_to_u32(const void* p) {
    uint32_t a;
    asm("{ .reg .u64 t; cvta.to.shared.u64 t, %1; cvt.u32.u64 %0, t; }"
        : "=r"(a) : "l"(p));
    return a;
}
__device__ __forceinline__ void ldsm_x4(uint32_t addr, uint32_t* r) {
    asm volatile("ldmatrix.sync.aligned.m8n8.x4.shared.b16 {%0,%1,%2,%3}, [%4];"
        : "=r"(r[0]), "=r"(r[1]), "=r"(r[2]), "=r"(r[3]) : "r"(addr));
}
__device__ __forceinline__ void ldsm_x4_t(uint32_t addr, uint32_t* r) {
    asm volatile("ldmatrix.sync.aligned.m8n8.x4.trans.shared.b16 {%0,%1,%2,%3}, [%4];"
        : "=r"(r[0]), "=r"(r[1]), "=r"(r[2]), "=r"(r[3]) : "r"(addr));
}
__device__ __forceinline__ void mma_f16(float* d, const uint32_t* a,
                                        uint32_t b0, uint32_t b1) {
    asm volatile(
        "mma.sync.aligned.m16n8k16.row.col.f32.f16.f16.f32 "
        "{%0,%1,%2,%3}, {%4,%5,%6,%7}, {%8,%9}, {%0,%1,%2,%3};"
        : "+f"(d[0]), "+f"(d[1]), "+f"(d[2]), "+f"(d[3])
        : "r"(a[0]), "r"(a[1]), "r"(a[2]), "r"(a[3]), "r"(b0), "r"(b1));
}
__device__ __forceinline__ uint32_t pkh(float lo, float hi) {
    uint32_t r;
    asm("cvt.rn.f16x2.f32 %0, %1, %2;" : "=r"(r) : "f"(hi), "f"(lo));
    return r;
}
__device__ __forceinline__ float ex2(float x) {
    float r;
    asm("ex2.approx.ftz.f32 %0, %1;" : "=f"(r) : "f"(x));
    return r;
}
__device__ __forceinline__ void cpasync16(uint32_t dst, const void* src) {
    asm volatile("cp.async.cg.shared.global [%0], [%1], 16;"
                 :: "r"(dst), "l"(src));
}
#define CP_COMMIT() asm volatile("cp.async.commit_group;" ::: "memory")
#define CP_WAIT1()  asm volatile("cp.async.wait_group 1;" ::: "memory")
#define CP_WAIT0()  asm volatile("cp.async.wait_group 0;" ::: "memory")

// softmax scale in base-2 domain: 1/sqrt(64) * log2(e)
#define CSC 0.18033688011112042f

// ---------------------------------------------------------------------------
// Unified prep kernel (one launch): blocks [0,2048) convert X,
// [2048,2816) transpose Wq/Wk/Wv, [2816,3072) transpose Wo.
// ---------------------------------------------------------------------------
__global__ __launch_bounds__(256) void conv_all_kernel(
    const float4* __restrict__ X4,
    const float* __restrict__ Wq, const float* __restrict__ Wk,
    const float* __restrict__ Wv, const float* __restrict__ Wo)
{
    __shared__ float ts[64][65];
    const int bx  = blockIdx.x;
    const int tid = threadIdx.x;

    if (bx < 2048) {
        int i0 = bx * 256 + tid;
        #pragma unroll
        for (int l = 0; l < 2; l++) {
            int i = i0 + l * 524288;
            float4 v = X4[i];
            union { float2 f; __half h[4]; } o;
            o.h[0] = __float2half_rn(v.x);
            o.h[1] = __float2half_rn(v.y);
            o.h[2] = __float2half_rn(v.z);
            o.h[3] = __float2half_rn(v.w);
            ((float2*)g_x)[i] = o.f;
        }
        return;
    }

    if (bx < 2816) {
        const int widx = bx - 2048;
        const int k0   = (widx & 15) * 64;
        const int h    = (widx >> 4) & 15;
        const int proj = widx >> 8;
        const float* W = (proj == 0) ? Wq : (proj == 1) ? Wk : Wv;
        W += (size_t)h * DD * DKH;
        #pragma unroll
        for (int l = 0; l < 4; l++) {
            int idx = tid + l * 256;
            int r = idx >> 4, c4 = idx & 15;
            float4 v = *(const float4*)&W[(size_t)(k0 + r) * DKH + c4 * 4];
            ts[r][c4 * 4 + 0] = v.x;
            ts[r][c4 * 4 + 1] = v.y;
            ts[r][c4 * 4 + 2] = v.z;
            ts[r][c4 * 4 + 3] = v.w;
        }
        __syncthreads();
        #pragma unroll
        for (int l = 0; l < 4; l++) {
            int idx = tid + l * 256;
            int nr = idx >> 4, kc = idx & 15;
            size_t orow = ((size_t)(proj * HH + h) * DKH + nr) * DD + k0 + kc * 4;
            #pragma unroll
            for (int j = 0; j < 4; j++)
                g_w[orow + j] = __float2half_rn(ts[kc * 4 + j][nr]);
        }
        return;
    }

    {
        const int widx = bx - 2816;
        const int k0 = (widx & 15) * 64;
        const int n0 = (widx >> 4) * 64;
        #pragma unroll
        for (int l = 0; l < 4; l++) {
            int idx = tid + l * 256;
            int r = idx >> 4, c4 = idx & 15;
            float4 v = *(const float4*)&Wo[(size_t)(k0 + r) * DD + n0 + c4 * 4];
            ts[r][c4 * 4 + 0] = v.x;
            ts[r][c4 * 4 + 1] = v.y;
            ts[r][c4 * 4 + 2] = v.z;
            ts[r][c4 * 4 + 3] = v.w;
        }
        __syncthreads();
        #pragma unroll
        for (int l = 0; l < 4; l++) {
            int idx = tid + l * 256;
            int nr = idx >> 4, kc = idx & 15;
            size_t orow = (size_t)(n0 + nr) * DD + k0 + kc * 4;
            #pragma unroll
            for (int j = 0; j < 4; j++)
                g_wo[orow + j] = __float2half_rn(ts[kc * 4 + j][nr]);
        }
    }
}

// ---------------------------------------------------------------------------
// Pipelined GEMM: M128 x N128 CTA, K chunks of 64, 2 stages, 2 tiles/stage
// (A | B), single-pass fp16. Warp tile 64x32 (2M x 4N). 2 CTAs/SM.
// ---------------------------------------------------------------------------
#define CROWB 144                 // 64 fp16 = 128B + 16B pad
#define CTILE (128 * CROWB)       // 18432
#define CSTAGE (2 * CTILE)        // 36864
#define GSM_BYTES (2 * CSTAGE)    // 73728

__device__ __forceinline__ void load_stage_g(
    uint32_t sm, const __half* __restrict__ A, const __half* __restrict__ B,
    int k0, int tid)
{
    #pragma unroll
    for (int l = 0; l < 4; l++) {
        int idx = tid + l * 256;
        int r = idx >> 3, c = idx & 7;
        uint32_t dof = (uint32_t)(r * CROWB + c * 16);
        size_t   sof = ((size_t)r * DD + k0) * 2 + c * 16;
        cpasync16(sm + 0 * CTILE + dof, (const char*)A + sof);
        cpasync16(sm + 1 * CTILE + dof, (const char*)B + sof);
    }
}

__device__ __forceinline__ void gemm_body(
    uint32_t smem_base, uint32_t a_lane, uint32_t b_lane,
    const __half* A, const __half* B, int tid, float acc[4][4][4])
{
    load_stage_g(smem_base,          A, B, 0,  tid);
    CP_COMMIT();
    load_stage_g(smem_base + CSTAGE, A, B, 64, tid);
    CP_COMMIT();

    for (int ch = 0; ch < 16; ch++) {
        if (ch >= 14) { CP_WAIT0(); } else { CP_WAIT1(); }
        __syncthreads();
        const uint32_t st = smem_base + (uint32_t)(ch & 1) * CSTAGE;

        #pragma unroll
        for (int ks = 0; ks < 4; ks++) {
            const uint32_t koff = ks * 32;
            uint32_t a[4][4];
            #pragma unroll
            for (int am = 0; am < 4; am++)
                ldsm_x4(st + 0 * CTILE + a_lane + am * 16 * CROWB + koff, a[am]);
            uint32_t b[2][4];
            #pragma unroll
            for (int bn = 0; bn < 2; bn++)
                ldsm_x4(st + 1 * CTILE + b_lane + bn * 16 * CROWB + koff, b[bn]);

            #pragma unroll
            for (int am = 0; am < 4; am++)
                #pragma unroll
                for (int bn = 0; bn < 2; bn++) {
                    mma_f16(acc[am][2*bn],   a[am], b[bn][0], b[bn][2]);
                    mma_f16(acc[am][2*bn+1], a[am], b[bn][1], b[bn][3]);
                }
        }
        __syncthreads();
        if (ch + 2 < 16) {
            load_stage_g(smem_base + (uint32_t)(ch & 1) * CSTAGE,
                         A, B, (ch + 2) * 64, tid);
            CP_COMMIT();
        }
    }
}

// ---------------------------------------------------------------------------
// QKV GEMM: Q/K/V -> single fp16. 2 CTAs/SM.
// ---------------------------------------------------------------------------
__global__ __launch_bounds__(256, 2) void qkv_mma_kernel(
    const float* __restrict__ bq, const float* __restrict__ bk,
    const float* __restrict__ bv)
{
    extern __shared__ char smem[];
    const uint32_t smem_base = smem_to_u32(smem);
    const int tid  = threadIdx.x;
    const int lane = tid & 31;
    const int wid  = tid >> 5;
    const int warpM = wid & 1;          // 2 groups x 64 rows
    const int warpN = wid >> 1;         // 4 groups x 32 cols

    const int m0   = blockIdx.x * 128;
    const int hg   = blockIdx.y;
    const int proj = blockIdx.z;

    const float* bias = (proj == 0) ? bq : (proj == 1) ? bk : bv;
    __half* outp = (proj == 0) ? g_q : (proj == 1) ? g_k : g_v;

    const size_t brow = ((size_t)proj * HH * DKH + (size_t)hg * 128) * DD;

    float acc[4][4][4] = {};

    const int lrow  = lane & 15;
    const int lhalf = lane >> 4;
    const uint32_t a_lane = (uint32_t)((warpM * 64 + lrow) * CROWB + lhalf * 16);
    const uint32_t b_lane = (uint32_t)((warpN * 32 + lrow) * CROWB + lhalf * 16);

    gemm_body(smem_base, a_lane, b_lane,
              g_x + (size_t)m0 * DD, g_w + brow, tid, acc);

    #pragma unroll
    for (int am = 0; am < 4; am++) {
        #pragma unroll
        for (int rh = 0; rh < 2; rh++) {
            const int token = m0 + warpM * 64 + am * 16 + rh * 8 + (lane >> 2);
            const int b_ = token >> 11;
            const int s_ = token & (SS - 1);
            #pragma unroll
            for (int na = 0; na < 4; na++) {
                const int ng = hg * 128 + warpN * 32 + na * 8 + (lane & 3) * 2;
                const int h  = ng >> 6;
                const int dk = ng & 63;
                float v0 = acc[am][na][rh*2+0] + __ldg(&bias[h*DKH + dk]);
                float v1 = acc[am][na][rh*2+1] + __ldg(&bias[h*DKH + dk+1]);
                union { __half2 b2; uint32_t u; } t;
                t.u = pkh(v0, v1);
                *(__half2*)&outp[((size_t)(b_ * HH + h) * SS + s_) * DKH + dk] = t.b2;
            }
        }
    }
}

// ---------------------------------------------------------------------------
// Output projection: out = ctx @ Wo + bo (fp32 out). Single-pass. 2 CTAs/SM.
// ---------------------------------------------------------------------------
__global__ __launch_bounds__(256, 2) void out_mma_kernel(
    const float* __restrict__ bo, float* __restrict__ out)
{
    extern __shared__ char smem[];
    const uint32_t smem_base = smem_to_u32(smem);
    const int tid  = threadIdx.x;
    const int lane = tid & 31;
    const int wid  = tid >> 5;
    const int warpM = wid & 1;
    const int warpN = wid >> 1;

    const int m0 = blockIdx.x * 128;
    const int n0 = blockIdx.y * 128;

    float acc[4][4][4] = {};

    const int lrow  = lane & 15;
    const int lhalf = lane >> 4;
    const uint32_t a_lane = (uint32_t)((warpM * 64 + lrow) * CROWB + lhalf * 16);
    const uint32_t b_lane = (uint32_t)((warpN * 32 + lrow) * CROWB + lhalf * 16);

    gemm_body(smem_base, a_lane, b_lane,
              g_c + (size_t)m0 * DD, g_wo + (size_t)n0 * DD, tid, acc);

    #pragma unroll
    for (int am = 0; am < 4; am++) {
        #pragma unroll
        for (int rh = 0; rh < 2; rh++) {
            const int token = m0 + warpM * 64 + am * 16 + rh * 8 + (lane >> 2);
            #pragma unroll
            for (int na = 0; na < 4; na++) {
                const int n = n0 + warpN * 32 + na * 8 + (lane & 3) * 2;
                float2 o;
                o.x = acc[am][na][rh*2+0] + __ldg(&bo[n]);
                o.y = acc[am][na][rh*2+1] + __ldg(&bo[n+1]);
                *(float2*)&out[(size_t)token * DD + n] = o;
            }
        }
    }
}

// ---------------------------------------------------------------------------
// Flash attention: 32 q-rows/warp (q-tile 256), grid (8, 32), block 256.
// K/V chunks of 128 keys (2 sub-chunks of 64), 2 stages. Base-2 softmax.
// ---------------------------------------------------------------------------
#define AROWB 144                     // 72 fp16 per row
#define ATILE (128 * AROWB)           // 18432 (128-key tile)
#define AST (2 * ATILE)               // 36864 : K | V
#define ATTN_SM_BYTES (2 * AST)       // 73728

__device__ __forceinline__ void attn_load_stage(
    uint32_t sm, size_t key0, int tid)
{
    #pragma unroll
    for (int l = 0; l < 4; l++) {
        int idx = tid + l * 256;
        int r = idx >> 3, c = idx & 7;
        uint32_t dof = (uint32_t)(r * AROWB + c * 16);
        size_t   sof = ((size_t)r * DKH) * 2 + c * 16;
        cpasync16(sm + 0 * ATILE + dof, (const char*)(g_k + key0) + sof);
        cpasync16(sm + 1 * ATILE + dof, (const char*)(g_v + key0) + sof);
    }
}

__global__ __launch_bounds__(256, 1) void attn_mma_kernel()
{
    extern __shared__ char smem[];
    const uint32_t smem_base = smem_to_u32(smem);
    const int tid  = threadIdx.x;
    const int lane = tid & 31;
    const int w    = tid >> 5;          // warp 0..7 -> q rows w*32..w*32+31

    const int bh = blockIdx.y;
    const int q0 = blockIdx.x * 256;
    const size_t base = (size_t)bh * SS * DKH;

    const int lrow  = lane & 15;
    const int lhalf = lane >> 4;

    // ---- stage Q (256 x 64) once; extract resident fragments ----
    uint32_t q[2][4][4];   // [am][ks][regs]
    {
        const __half* Qp = g_q + base + (size_t)q0 * DKH;
        #pragma unroll
        for (int l = 0; l < 8; l++) {
            int idx = tid + l * 256;
            int r = idx >> 3, c = idx & 7;
            cpasync16(smem_base + (uint32_t)(r * AROWB + c * 16),
                      (const char*)Qp + ((size_t)r * DKH) * 2 + c * 16);
        }
        CP_COMMIT();
        CP_WAIT0();
        __syncthreads();
        #pragma unroll
        for (int am = 0; am < 2; am++) {
            const uint32_t qa = smem_base +
                (uint32_t)((w * 32 + am * 16 + lrow) * AROWB + lhalf * 16);
            #pragma unroll
            for (int ks = 0; ks < 4; ks++)
                ldsm_x4(qa + ks * 32, q[am][ks]);
        }
        __syncthreads();
    }

    attn_load_stage(smem_base, base, tid);
    CP_COMMIT();
    attn_load_stage(smem_base + AST, base + (size_t)128 * DKH, tid);
    CP_COMMIT();

    float o[2][8][4] = {};
    float m[2][2], l[2][2];
    #pragma unroll
    for (int am = 0; am < 2; am++) {
        m[am][0] = -1e30f; m[am][1] = -1e30f;
        l[am][0] = 0.0f;   l[am][1] = 0.0f;
    }

    const uint32_t lane_off = (uint32_t)(lrow * AROWB + lhalf * 16);

    for (int ch = 0; ch < 16; ch++) {
        if (ch >= 14) { CP_WAIT0(); } else { CP_WAIT1(); }
        __syncthreads();
        const uint32_t st = smem_base + (uint32_t)(ch & 1) * AST;

        #pragma unroll
        for (int sub = 0; sub < 2; sub++) {
            const uint32_t kb = st + (uint32_t)(sub * 64 * AROWB) + lane_off;

            // ---- S = Q K^T : 32 x 64 per warp, single-pass ----
            float s[2][8][4] = {};
            #pragma unroll
            for (int ks = 0; ks < 4; ks++) {
                const uint32_t koff = ks * 32;
                uint32_t kh[4][4];
                #pragma unroll
                for (int bn = 0; bn < 4; bn++)
                    ldsm_x4(kb + bn * 16 * AROWB + koff, kh[bn]);
                #pragma unroll
                for (int bn = 0; bn < 4; bn++)
                    #pragma unroll
                    for (int am = 0; am < 2; am++) {
                        mma_f16(s[am][2*bn],   q[am][ks], kh[bn][0], kh[bn][2]);
                        mma_f16(s[am][2*bn+1], q[am][ks], kh[bn][1], kh[bn][3]);
                    }
            }

            // ---- online softmax (base-2, scale folded into exp FMA) ----
            #pragma unroll
            for (int am = 0; am < 2; am++) {
                float mxA = -1e30f, mxB = -1e30f;
                #pragma unroll
                for (int j = 0; j < 8; j++) {
                    mxA = fmaxf(mxA, fmaxf(s[am][j][0], s[am][j][1]));
                    mxB = fmaxf(mxB, fmaxf(s[am][j][2], s[am][j][3]));
                }
                #pragma unroll
                for (int msk = 1; msk < 4; msk <<= 1) {
                    mxA = fmaxf(mxA, __shfl_xor_sync(0xffffffffu, mxA, msk));
                    mxB = fmaxf(mxB, __shfl_xor_sync(0xffffffffu, mxB, msk));
                }
                const float mnA = fmaxf(m[am][0], mxA * CSC);
                const float mnB = fmaxf(m[am][1], mxB * CSC);
                const float fA = ex2(m[am][0] - mnA);
                const float fB = ex2(m[am][1] - mnB);
                m[am][0] = mnA; m[am][1] = mnB;
                float rsA = 0.0f, rsB = 0.0f;
                #pragma unroll
                for (int j = 0; j < 8; j++) {
                    s[am][j][0] = ex2(fmaf(s[am][j][0], CSC, -mnA)); rsA += s[am][j][0];
                    s[am][j][1] = ex2(fmaf(s[am][j][1], CSC, -mnA)); rsA += s[am][j][1];
                    s[am][j][2] = ex2(fmaf(s[am][j][2], CSC, -mnB)); rsB += s[am][j][2];
                    s[am][j][3] = ex2(fmaf(s[am][j][3], CSC, -mnB)); rsB += s[am][j][3];
                }
                #pragma unroll
                for (int msk = 1; msk < 4; msk <<= 1) {
                    rsA += __shfl_xor_sync(0xffffffffu, rsA, msk);
                    rsB += __shfl_xor_sync(0xffffffffu, rsB, msk);
                }
                l[am][0] = l[am][0] * fA + rsA;
                l[am][1] = l[am][1] * fB + rsB;
                #pragma unroll
                for (int j = 0; j < 8; j++) {
                    o[am][j][0] *= fA; o[am][j][1] *= fA;
                    o[am][j][2] *= fB; o[am][j][3] *= fB;
                }
            }

            // ---- O += P V : single-pass (P rounded to fp16) ----
            #pragma unroll
            for (int j = 0; j < 4; j++) {
                uint32_t ph[2][4];
                #pragma unroll
                for (int am = 0; am < 2; am++) {
                    ph[am][0] = pkh(s[am][2*j][0],   s[am][2*j][1]);
                    ph[am][1] = pkh(s[am][2*j][2],   s[am][2*j][3]);
                    ph[am][2] = pkh(s[am][2*j+1][0], s[am][2*j+1][1]);
                    ph[am][3] = pkh(s[am][2*j+1][2], s[am][2*j+1][3]);
                }
                const uint32_t vrow = st + 1 * ATILE +
                    (uint32_t)((sub * 64 + j * 16 + lrow) * AROWB + lhalf * 16);
                uint32_t vh[4][4];
                #pragma unroll
                for (int dvp = 0; dvp < 4; dvp++)
                    ldsm_x4_t(vrow + dvp * 32, vh[dvp]);
                #pragma unroll
                for (int dvp = 0; dvp < 4; dvp++)
                    #pragma unroll
                    for (int am = 0; am < 2; am++) {
                        mma_f16(o[am][2*dvp],   ph[am], vh[dvp][0], vh[dvp][1]);
                        mma_f16(o[am][2*dvp+1], ph[am], vh[dvp][2], vh[dvp][3]);
                    }
            }
        }
        __syncthreads();
        if (ch + 2 < 16) {
            attn_load_stage(smem_base + (uint32_t)(ch & 1) * AST,
                            base + (size_t)((ch + 2) * 128) * DKH, tid);
            CP_COMMIT();
        }
    }

    // ---- epilogue: normalize, write ctx single fp16 [token][1024] ----
    const int b_ = bh / HH;
    const int h_ = bh % HH;
    #pragma unroll
    for (int am = 0; am < 2; am++) {
        const float invA = 1.0f / l[am][0];
        const float invB = 1.0f / l[am][1];
        const int rA = q0 + w * 32 + am * 16 + (lane >> 2);
        const int tokenA = b_ * SS + rA;
        const int tokenB = tokenA + 8;
        #pragma unroll
        for (int jj = 0; jj < 8; jj++) {
            const int col = h_ * DKH + jj * 8 + (lane & 3) * 2;
            {
                union { __half2 b2; uint32_t u; } t;
                t.u = pkh(o[am][jj][0] * invA, o[am][jj][1] * invA);
                *(__half2*)&g_c[(size_t)tokenA * DD + col] = t.b2;
            }
            {
                union { __half2 b2; uint32_t u; } t;
                t.u = pkh(o[am][jj][2] * invB, o[am][jj][3] * invB);
                *(__half2*)&g_c[(size_t)tokenB * DD + col] = t.b2;
            }
        }
    }
}

// ---------------------------------------------------------------------------
extern "C" void kernel_launch(void* const* d_in, const int* in_sizes, int n_in,
                              void* d_out, int out_size)
{
    const float* X  = (const float*)d_in[0];
    const float* Wq = (const float*)d_in[1];
    const float* bq = (const float*)d_in[2];
    const float* Wk = (const float*)d_in[3];
    const float* bk = (const float*)d_in[4];
    const float* Wv = (const float*)d_in[5];
    const float* bv = (const float*)d_in[6];
    const float* Wo = (const float*)d_in[7];
    const float* bo = (const float*)d_in[8];
    float* out = (float*)d_out;

    cudaFuncSetAttribute(qkv_mma_kernel,
                         cudaFuncAttributeMaxDynamicSharedMemorySize, GSM_BYTES);
    cudaFuncSetAttribute(out_mma_kernel,
                         cudaFuncAttributeMaxDynamicSharedMemorySize, GSM_BYTES);
    cudaFuncSetAttribute(attn_mma_kernel,
                         cudaFuncAttributeMaxDynamicSharedMemorySize, ATTN_SM_BYTES);

    conv_all_kernel<<<3072, 256>>>((const float4*)X, Wq, Wk, Wv, Wo);
    qkv_mma_kernel<<<dim3(32, 8, 3), 256, GSM_BYTES>>>(bq, bk, bv);
    attn_mma_kernel<<<dim3(8, 32), 256, ATTN_SM_BYTES>>>();
    out_mma_kernel<<<dim3(32, 8), 256, GSM_BYTES>>>(bo, out);
}

// round 16
// speedup vs baseline: 1.5356x; 1.5356x over previous
#include <cuda_runtime.h>
#include <cuda_fp16.h>
#include <cstdint>

#define BB 2
#define SS 2048
#define DD 1024
#define HH 16
#define DKH 64
#define BHH (BB*HH)

// ---------------------------------------------------------------------------
// Scratch: single fp16 everywhere.
// ---------------------------------------------------------------------------
__device__ __half g_x [BB * SS * DD];
__device__ __half g_w [3 * HH * DKH * DD];   // [(proj*16+h)*64+n][k]
__device__ __half g_q [BHH * SS * DKH];      // [bh][s][64] (UNscaled)
__device__ __half g_k [BHH * SS * DKH];
__device__ __half g_v [BHH * SS * DKH];
__device__ __half g_c [BB * SS * HH * DKH];  // ctx [token][1024]
__device__ __half g_wo[DD * DD];             // Wo^T [n][k]

// ---------------------------------------------------------------------------
// Helpers
// ---------------------------------------------------------------------------
__device__ __forceinline__ uint32_t smem_to_u32(const void* p) {
    uint32_t a;
    asm("{ .reg .u64 t; cvta.to.shared.u64 t, %1; cvt.u32.u64 %0, t; }"
        : "=r"(a) : "l"(p));
    return a;
}
__device__ __forceinline__ void ldsm_x4(uint32_t addr, uint32_t* r) {
    asm volatile("ldmatrix.sync.aligned.m8n8.x4.shared.b16 {%0,%1,%2,%3}, [%4];"
        : "=r"(r[0]), "=r"(r[1]), "=r"(r[2]), "=r"(r[3]) : "r"(addr));
}
__device__ __forceinline__ void ldsm_x4_t(uint32_t addr, uint32_t* r) {
    asm volatile("ldmatrix.sync.aligned.m8n8.x4.trans.shared.b16 {%0,%1,%2,%3}, [%4];"
        : "=r"(r[0]), "=r"(r[1]), "=r"(r[2]), "=r"(r[3]) : "r"(addr));
}
__device__ __forceinline__ void mma_f16(float* d, const uint32_t* a,
                                        uint32_t b0, uint32_t b1) {
    asm volatile(
        "mma.sync.aligned.m16n8k16.row.col.f32.f16.f16.f32 "
        "{%0,%1,%2,%3}, {%4,%5,%6,%7}, {%8,%9}, {%0,%1,%2,%3};"
        : "+f"(d[0]), "+f"(d[1]), "+f"(d[2]), "+f"(d[3])
        : "r"(a[0]), "r"(a[1]), "r"(a[2]), "r"(a[3]), "r"(b0), "r"(b1));
}
__device__ __forceinline__ uint32_t pkh(float lo, float hi) {
    uint32_t r;
    asm("cvt.rn.f16x2.f32 %0, %1, %2;" : "=r"(r) : "f"(hi), "f"(lo));
    return r;
}
__device__ __forceinline__ float ex2(float x) {
    float r;
    asm("ex2.approx.ftz.f32 %0, %1;" : "=f"(r) : "f"(x));
    return r;
}
__device__ __forceinline__ void cpasync16(uint32_t dst, const void* src) {
    asm volatile("cp.async.cg.shared.global [%0], [%1], 16;"
                 :: "r"(dst), "l"(src));
}
#define CP_COMMIT() asm volatile("cp.async.commit_group;" ::: "memory")
#define CP_WAIT1()  asm volatile("cp.async.wait_group 1;" ::: "memory")
#define CP_WAIT0()  asm volatile("cp.async.wait_group 0;" ::: "memory")

// softmax scale in base-2 domain: 1/sqrt(64) * log2(e)
#define CSC 0.18033688011112042f

// ---------------------------------------------------------------------------
// Unified prep kernel (one launch): blocks [0,2048) convert X,
// [2048,2816) transpose Wq/Wk/Wv, [2816,3072) transpose Wo.
// ---------------------------------------------------------------------------
__global__ __launch_bounds__(256) void conv_all_kernel(
    const float4* __restrict__ X4,
    const float* __restrict__ Wq, const float* __restrict__ Wk,
    const float* __restrict__ Wv, const float* __restrict__ Wo)
{
    __shared__ float ts[64][65];
    const int bx  = blockIdx.x;
    const int tid = threadIdx.x;

    if (bx < 2048) {
        int i0 = bx * 256 + tid;
        #pragma unroll
        for (int l = 0; l < 2; l++) {
            int i = i0 + l * 524288;
            float4 v = X4[i];
            union { float2 f; __half h[4]; } o;
            o.h[0] = __float2half_rn(v.x);
            o.h[1] = __float2half_rn(v.y);
            o.h[2] = __float2half_rn(v.z);
            o.h[3] = __float2half_rn(v.w);
            ((float2*)g_x)[i] = o.f;
        }
        return;
    }

    if (bx < 2816) {
        const int widx = bx - 2048;
        const int k0   = (widx & 15) * 64;
        const int h    = (widx >> 4) & 15;
        const int proj = widx >> 8;
        const float* W = (proj == 0) ? Wq : (proj == 1) ? Wk : Wv;
        W += (size_t)h * DD * DKH;
        #pragma unroll
        for (int l = 0; l < 4; l++) {
            int idx = tid + l * 256;
            int r = idx >> 4, c4 = idx & 15;
            float4 v = *(const float4*)&W[(size_t)(k0 + r) * DKH + c4 * 4];
            ts[r][c4 * 4 + 0] = v.x;
            ts[r][c4 * 4 + 1] = v.y;
            ts[r][c4 * 4 + 2] = v.z;
            ts[r][c4 * 4 + 3] = v.w;
        }
        __syncthreads();
        #pragma unroll
        for (int l = 0; l < 4; l++) {
            int idx = tid + l * 256;
            int nr = idx >> 4, kc = idx & 15;
            size_t orow = ((size_t)(proj * HH + h) * DKH + nr) * DD + k0 + kc * 4;
            #pragma unroll
            for (int j = 0; j < 4; j++)
                g_w[orow + j] = __float2half_rn(ts[kc * 4 + j][nr]);
        }
        return;
    }

    {
        const int widx = bx - 2816;
        const int k0 = (widx & 15) * 64;
        const int n0 = (widx >> 4) * 64;
        #pragma unroll
        for (int l = 0; l < 4; l++) {
            int idx = tid + l * 256;
            int r = idx >> 4, c4 = idx & 15;
            float4 v = *(const float4*)&Wo[(size_t)(k0 + r) * DD + n0 + c4 * 4];
            ts[r][c4 * 4 + 0] = v.x;
            ts[r][c4 * 4 + 1] = v.y;
            ts[r][c4 * 4 + 2] = v.z;
            ts[r][c4 * 4 + 3] = v.w;
        }
        __syncthreads();
        #pragma unroll
        for (int l = 0; l < 4; l++) {
            int idx = tid + l * 256;
            int nr = idx >> 4, kc = idx & 15;
            size_t orow = (size_t)(n0 + nr) * DD + k0 + kc * 4;
            #pragma unroll
            for (int j = 0; j < 4; j++)
                g_wo[orow + j] = __float2half_rn(ts[kc * 4 + j][nr]);
        }
    }
}

// ---------------------------------------------------------------------------
// Pipelined GEMM: M128 x N128 CTA, K chunks of 64, 2 stages, 2 tiles/stage
// (A | B), single-pass fp16. Warp tile 64x32 (2M x 4N). 2 CTAs/SM.
// ---------------------------------------------------------------------------
#define CROWB 144                 // 64 fp16 = 128B + 16B pad
#define CTILE (128 * CROWB)       // 18432
#define CSTAGE (2 * CTILE)        // 36864
#define GSM_BYTES (2 * CSTAGE)    // 73728

__device__ __forceinline__ void load_stage_g(
    uint32_t sm, const __half* __restrict__ A, const __half* __restrict__ B,
    int k0, int tid)
{
    #pragma unroll
    for (int l = 0; l < 4; l++) {
        int idx = tid + l * 256;
        int r = idx >> 3, c = idx & 7;
        uint32_t dof = (uint32_t)(r * CROWB + c * 16);
        size_t   sof = ((size_t)r * DD + k0) * 2 + c * 16;
        cpasync16(sm + 0 * CTILE + dof, (const char*)A + sof);
        cpasync16(sm + 1 * CTILE + dof, (const char*)B + sof);
    }
}

__device__ __forceinline__ void gemm_body(
    uint32_t smem_base, uint32_t a_lane, uint32_t b_lane,
    const __half* A, const __half* B, int tid, float acc[4][4][4])
{
    load_stage_g(smem_base,          A, B, 0,  tid);
    CP_COMMIT();
    load_stage_g(smem_base + CSTAGE, A, B, 64, tid);
    CP_COMMIT();

    for (int ch = 0; ch < 16; ch++) {
        if (ch >= 14) { CP_WAIT0(); } else { CP_WAIT1(); }
        __syncthreads();
        const uint32_t st = smem_base + (uint32_t)(ch & 1) * CSTAGE;

        #pragma unroll
        for (int ks = 0; ks < 4; ks++) {
            const uint32_t koff = ks * 32;
            uint32_t a[4][4];
            #pragma unroll
            for (int am = 0; am < 4; am++)
                ldsm_x4(st + 0 * CTILE + a_lane + am * 16 * CROWB + koff, a[am]);
            uint32_t b[2][4];
            #pragma unroll
            for (int bn = 0; bn < 2; bn++)
                ldsm_x4(st + 1 * CTILE + b_lane + bn * 16 * CROWB + koff, b[bn]);

            #pragma unroll
            for (int am = 0; am < 4; am++)
                #pragma unroll
                for (int bn = 0; bn < 2; bn++) {
                    mma_f16(acc[am][2*bn],   a[am], b[bn][0], b[bn][2]);
                    mma_f16(acc[am][2*bn+1], a[am], b[bn][1], b[bn][3]);
                }
        }
        __syncthreads();
        if (ch + 2 < 16) {
            load_stage_g(smem_base + (uint32_t)(ch & 1) * CSTAGE,
                         A, B, (ch + 2) * 64, tid);
            CP_COMMIT();
        }
    }
}

// ---------------------------------------------------------------------------
// QKV GEMM: Q/K/V -> single fp16. 2 CTAs/SM.
// ---------------------------------------------------------------------------
__global__ __launch_bounds__(256, 2) void qkv_mma_kernel(
    const float* __restrict__ bq, const float* __restrict__ bk,
    const float* __restrict__ bv)
{
    extern __shared__ char smem[];
    const uint32_t smem_base = smem_to_u32(smem);
    const int tid  = threadIdx.x;
    const int lane = tid & 31;
    const int wid  = tid >> 5;
    const int warpM = wid & 1;          // 2 groups x 64 rows
    const int warpN = wid >> 1;         // 4 groups x 32 cols

    const int m0   = blockIdx.x * 128;
    const int hg   = blockIdx.y;
    const int proj = blockIdx.z;

    const float* bias = (proj == 0) ? bq : (proj == 1) ? bk : bv;
    __half* outp = (proj == 0) ? g_q : (proj == 1) ? g_k : g_v;

    const size_t brow = ((size_t)proj * HH * DKH + (size_t)hg * 128) * DD;

    float acc[4][4][4] = {};

    const int lrow  = lane & 15;
    const int lhalf = lane >> 4;
    const uint32_t a_lane = (uint32_t)((warpM * 64 + lrow) * CROWB + lhalf * 16);
    const uint32_t b_lane = (uint32_t)((warpN * 32 + lrow) * CROWB + lhalf * 16);

    gemm_body(smem_base, a_lane, b_lane,
              g_x + (size_t)m0 * DD, g_w + brow, tid, acc);

    #pragma unroll
    for (int am = 0; am < 4; am++) {
        #pragma unroll
        for (int rh = 0; rh < 2; rh++) {
            const int token = m0 + warpM * 64 + am * 16 + rh * 8 + (lane >> 2);
            const int b_ = token >> 11;
            const int s_ = token & (SS - 1);
            #pragma unroll
            for (int na = 0; na < 4; na++) {
                const int ng = hg * 128 + warpN * 32 + na * 8 + (lane & 3) * 2;
                const int h  = ng >> 6;
                const int dk = ng & 63;
                float v0 = acc[am][na][rh*2+0] + __ldg(&bias[h*DKH + dk]);
                float v1 = acc[am][na][rh*2+1] + __ldg(&bias[h*DKH + dk+1]);
                union { __half2 b2; uint32_t u; } t;
                t.u = pkh(v0, v1);
                *(__half2*)&outp[((size_t)(b_ * HH + h) * SS + s_) * DKH + dk] = t.b2;
            }
        }
    }
}

// ---------------------------------------------------------------------------
// Output projection: out = ctx @ Wo + bo (fp32 out). Single-pass. 2 CTAs/SM.
// ---------------------------------------------------------------------------
__global__ __launch_bounds__(256, 2) void out_mma_kernel(
    const float* __restrict__ bo, float* __restrict__ out)
{
    extern __shared__ char smem[];
    const uint32_t smem_base = smem_to_u32(smem);
    const int tid  = threadIdx.x;
    const int lane = tid & 31;
    const int wid  = tid >> 5;
    const int warpM = wid & 1;
    const int warpN = wid >> 1;

    const int m0 = blockIdx.x * 128;
    const int n0 = blockIdx.y * 128;

    float acc[4][4][4] = {};

    const int lrow  = lane & 15;
    const int lhalf = lane >> 4;
    const uint32_t a_lane = (uint32_t)((warpM * 64 + lrow) * CROWB + lhalf * 16);
    const uint32_t b_lane = (uint32_t)((warpN * 32 + lrow) * CROWB + lhalf * 16);

    gemm_body(smem_base, a_lane, b_lane,
              g_c + (size_t)m0 * DD, g_wo + (size_t)n0 * DD, tid, acc);

    #pragma unroll
    for (int am = 0; am < 4; am++) {
        #pragma unroll
        for (int rh = 0; rh < 2; rh++) {
            const int token = m0 + warpM * 64 + am * 16 + rh * 8 + (lane >> 2);
            #pragma unroll
            for (int na = 0; na < 4; na++) {
                const int n = n0 + warpN * 32 + na * 8 + (lane & 3) * 2;
                float2 o;
                o.x = acc[am][na][rh*2+0] + __ldg(&bo[n]);
                o.y = acc[am][na][rh*2+1] + __ldg(&bo[n+1]);
                *(float2*)&out[(size_t)token * DD + n] = o;
            }
        }
    }
}

// ---------------------------------------------------------------------------
// Flash attention: 32 q-rows/warp (q-tile 256), grid (8, 32), block 256.
// K/V chunks of 64 keys, 2 stages (36 KB smem -> 2 CTAs/SM co-residency).
// Base-2 softmax: scale folded into exp FMA, ex2.approx.
// ---------------------------------------------------------------------------
#define AROWB 144                    // 72 fp16 per row
#define ATILE (64 * AROWB)           // 9216
#define AST (2 * ATILE)              // 18432 : K | V
#define ATTN_SM_BYTES (2 * AST)      // 36864

__device__ __forceinline__ void attn_load_stage(
    uint32_t sm, size_t key0, int tid)
{
    #pragma unroll
    for (int l = 0; l < 2; l++) {
        int idx = tid + l * 256;
        int r = idx >> 3, c = idx & 7;
        uint32_t dof = (uint32_t)(r * AROWB + c * 16);
        size_t   sof = ((size_t)r * DKH) * 2 + c * 16;
        cpasync16(sm + 0 * ATILE + dof, (const char*)(g_k + key0) + sof);
        cpasync16(sm + 1 * ATILE + dof, (const char*)(g_v + key0) + sof);
    }
}

__global__ __launch_bounds__(256, 1) void attn_mma_kernel()
{
    extern __shared__ char smem[];
    const uint32_t smem_base = smem_to_u32(smem);
    const int tid  = threadIdx.x;
    const int lane = tid & 31;
    const int w    = tid >> 5;          // warp 0..7 -> q rows w*32..w*32+31

    const int bh = blockIdx.y;
    const int q0 = blockIdx.x * 256;
    const size_t base = (size_t)bh * SS * DKH;

    const int lrow  = lane & 15;
    const int lhalf = lane >> 4;

    // ---- stage Q (256 x 64) once; extract resident fragments ----
    uint32_t q[2][4][4];   // [am][ks][regs]
    {
        const __half* Qp = g_q + base + (size_t)q0 * DKH;
        #pragma unroll
        for (int l = 0; l < 8; l++) {
            int idx = tid + l * 256;
            int r = idx >> 3, c = idx & 7;
            cpasync16(smem_base + (uint32_t)(r * AROWB + c * 16),
                      (const char*)Qp + ((size_t)r * DKH) * 2 + c * 16);
        }
        CP_COMMIT();
        CP_WAIT0();
        __syncthreads();
        #pragma unroll
        for (int am = 0; am < 2; am++) {
            const uint32_t qa = smem_base +
                (uint32_t)((w * 32 + am * 16 + lrow) * AROWB + lhalf * 16);
            #pragma unroll
            for (int ks = 0; ks < 4; ks++)
                ldsm_x4(qa + ks * 32, q[am][ks]);
        }
        __syncthreads();
    }

    attn_load_stage(smem_base, base, tid);
    CP_COMMIT();
    attn_load_stage(smem_base + AST, base + (size_t)64 * DKH, tid);
    CP_COMMIT();

    float o[2][8][4] = {};
    float m[2][2], l[2][2];
    #pragma unroll
    for (int am = 0; am < 2; am++) {
        m[am][0] = -1e30f; m[am][1] = -1e30f;
        l[am][0] = 0.0f;   l[am][1] = 0.0f;
    }

    const uint32_t lane_off = (uint32_t)(lrow * AROWB + lhalf * 16);

    for (int ch = 0; ch < 32; ch++) {
        if (ch >= 30) { CP_WAIT0(); } else { CP_WAIT1(); }
        __syncthreads();
        const uint32_t st = smem_base + (uint32_t)(ch & 1) * AST;
        const uint32_t kb = st + lane_off;

        // ---- S = Q K^T : 32 x 64 per warp, single-pass ----
        float s[2][8][4] = {};
        #pragma unroll
        for (int ks = 0; ks < 4; ks++) {
            const uint32_t koff = ks * 32;
            uint32_t kh[4][4];
            #pragma unroll
            for (int bn = 0; bn < 4; bn++)
                ldsm_x4(kb + bn * 16 * AROWB + koff, kh[bn]);
            #pragma unroll
            for (int bn = 0; bn < 4; bn++)
                #pragma unroll
                for (int am = 0; am < 2; am++) {
                    mma_f16(s[am][2*bn],   q[am][ks], kh[bn][0], kh[bn][2]);
                    mma_f16(s[am][2*bn+1], q[am][ks], kh[bn][1], kh[bn][3]);
                }
        }

        // ---- online softmax (base-2, scale folded into exp FMA) ----
        #pragma unroll
        for (int am = 0; am < 2; am++) {
            float mxA = -1e30f, mxB = -1e30f;
            #pragma unroll
            for (int j = 0; j < 8; j++) {
                mxA = fmaxf(mxA, fmaxf(s[am][j][0], s[am][j][1]));
                mxB = fmaxf(mxB, fmaxf(s[am][j][2], s[am][j][3]));
            }
            #pragma unroll
            for (int msk = 1; msk < 4; msk <<= 1) {
                mxA = fmaxf(mxA, __shfl_xor_sync(0xffffffffu, mxA, msk));
                mxB = fmaxf(mxB, __shfl_xor_sync(0xffffffffu, mxB, msk));
            }
            const float mnA = fmaxf(m[am][0], mxA * CSC);
            const float mnB = fmaxf(m[am][1], mxB * CSC);
            const float fA = ex2(m[am][0] - mnA);
            const float fB = ex2(m[am][1] - mnB);
            m[am][0] = mnA; m[am][1] = mnB;
            float rsA = 0.0f, rsB = 0.0f;
            #pragma unroll
            for (int j = 0; j < 8; j++) {
                s[am][j][0] = ex2(fmaf(s[am][j][0], CSC, -mnA)); rsA += s[am][j][0];
                s[am][j][1] = ex2(fmaf(s[am][j][1], CSC, -mnA)); rsA += s[am][j][1];
                s[am][j][2] = ex2(fmaf(s[am][j][2], CSC, -mnB)); rsB += s[am][j][2];
                s[am][j][3] = ex2(fmaf(s[am][j][3], CSC, -mnB)); rsB += s[am][j][3];
            }
            #pragma unroll
            for (int msk = 1; msk < 4; msk <<= 1) {
                rsA += __shfl_xor_sync(0xffffffffu, rsA, msk);
                rsB += __shfl_xor_sync(0xffffffffu, rsB, msk);
            }
            l[am][0] = l[am][0] * fA + rsA;
            l[am][1] = l[am][1] * fB + rsB;
            #pragma unroll
            for (int j = 0; j < 8; j++) {
                o[am][j][0] *= fA; o[am][j][1] *= fA;
                o[am][j][2] *= fB; o[am][j][3] *= fB;
            }
        }

        // ---- O += P V : single-pass (P rounded to fp16) ----
        #pragma unroll
        for (int j = 0; j < 4; j++) {
            uint32_t ph[2][4];
            #pragma unroll
            for (int am = 0; am < 2; am++) {
                ph[am][0] = pkh(s[am][2*j][0],   s[am][2*j][1]);
                ph[am][1] = pkh(s[am][2*j][2],   s[am][2*j][3]);
                ph[am][2] = pkh(s[am][2*j+1][0], s[am][2*j+1][1]);
                ph[am][3] = pkh(s[am][2*j+1][2], s[am][2*j+1][3]);
            }
            const uint32_t vrow = st + 1 * ATILE +
                (uint32_t)((j * 16 + lrow) * AROWB + lhalf * 16);
            uint32_t vh[4][4];
            #pragma unroll
            for (int dvp = 0; dvp < 4; dvp++)
                ldsm_x4_t(vrow + dvp * 32, vh[dvp]);
            #pragma unroll
            for (int dvp = 0; dvp < 4; dvp++)
                #pragma unroll
                for (int am = 0; am < 2; am++) {
                    mma_f16(o[am][2*dvp],   ph[am], vh[dvp][0], vh[dvp][1]);
                    mma_f16(o[am][2*dvp+1], ph[am], vh[dvp][2], vh[dvp][3]);
                }
        }
        __syncthreads();
        if (ch + 2 < 32) {
            attn_load_stage(smem_base + (uint32_t)(ch & 1) * AST,
                            base + (size_t)((ch + 2) * 64) * DKH, tid);
            CP_COMMIT();
        }
    }

    // ---- epilogue: normalize, write ctx single fp16 [token][1024] ----
    const int b_ = bh / HH;
    const int h_ = bh % HH;
    #pragma unroll
    for (int am = 0; am < 2; am++) {
        const float invA = 1.0f / l[am][0];
        const float invB = 1.0f / l[am][1];
        const int rA = q0 + w * 32 + am * 16 + (lane >> 2);
        const int tokenA = b_ * SS + rA;
        const int tokenB = tokenA + 8;
        #pragma unroll
        for (int jj = 0; jj < 8; jj++) {
            const int col = h_ * DKH + jj * 8 + (lane & 3) * 2;
            {
                union { __half2 b2; uint32_t u; } t;
                t.u = pkh(o[am][jj][0] * invA, o[am][jj][1] * invA);
                *(__half2*)&g_c[(size_t)tokenA * DD + col] = t.b2;
            }
            {
                union { __half2 b2; uint32_t u; } t;
                t.u = pkh(o[am][jj][2] * invB, o[am][jj][3] * invB);
                *(__half2*)&g_c[(size_t)tokenB * DD + col] = t.b2;
            }
        }
    }
}

// ---------------------------------------------------------------------------
extern "C" void kernel_launch(void* const* d_in, const int* in_sizes, int n_in,
                              void* d_out, int out_size)
{
    const float* X  = (const float*)d_in[0];
    const float* Wq = (const float*)d_in[1];
    const float* bq = (const float*)d_in[2];
    const float* Wk = (const float*)d_in[3];
    const float* bk = (const float*)d_in[4];
    const float* Wv = (const float*)d_in[5];
    const float* bv = (const float*)d_in[6];
    const float* Wo = (const float*)d_in[7];
    const float* bo = (const float*)d_in[8];
    float* out = (float*)d_out;

    cudaFuncSetAttribute(qkv_mma_kernel,
                         cudaFuncAttributeMaxDynamicSharedMemorySize, GSM_BYTES);
    cudaFuncSetAttribute(out_mma_kernel,
                         cudaFuncAttributeMaxDynamicSharedMemorySize, GSM_BYTES);
    cudaFuncSetAttribute(attn_mma_kernel,
                         cudaFuncAttributeMaxDynamicSharedMemorySize, ATTN_SM_BYTES);

    conv_all_kernel<<<3072, 256>>>((const float4*)X, Wq, Wk, Wv, Wo);
    qkv_mma_kernel<<<dim3(32, 8, 3), 256, GSM_BYTES>>>(bq, bk, bv);
    attn_mma_kernel<<<dim3(8, 32), 256, ATTN_SM_BYTES>>>();
    out_mma_kernel<<<dim3(32, 8), 256, GSM_BYTES>>>(bo, out);
}